// round 3
// baseline (speedup 1.0000x reference)
#include <cuda_runtime.h>
#include <math.h>

#define HID   1024
#define BSZ   16
#define NOPT  4
#define ROWS  (BSZ*NOPT)    // 64
#define TRUN  2
#define SEQ   1536
#define PLEN  512
#define QLEN  128

#define KSPLIT 32
#define KCHUNK (HID/KSPLIT)   // 32
#define NTILE  64

// Scratch (device globals — no allocation allowed)
__device__ float g_feats[ROWS*HID];
__device__ float g_h1[ROWS*HID];
__device__ float g_h2[ROWS*HID];

// ---------------------------------------------------------------------------
// opt_length dtype-robust read (harness may store int32 or int64)
// ---------------------------------------------------------------------------
__device__ __forceinline__ long long opt_at(const void* p, bool is64, int i) {
    if (is64) return ((const long long*)p)[i];
    return (long long)((const int*)p)[i];
}

// ---------------------------------------------------------------------------
// 1) prep: blocks [0,256): init g_h1/g_h2 with biases; blocks [256,320): feats
// ---------------------------------------------------------------------------
__global__ void prep_kernel(const float* __restrict__ emb,
                            const void* __restrict__ opt_length,
                            const float* __restrict__ b1,
                            const float* __restrict__ b2) {
    if (blockIdx.x < 256) {
        int i = blockIdx.x * 256 + threadIdx.x;     // 0..65535
        int j = i & (HID - 1);
        g_h1[i] = b1[j];
        g_h2[i] = b2[j];
        return;
    }
    int row = blockIdx.x - 256;      // b*NOPT + o
    int b = row >> 2, o = row & 3;

    bool is64 = (((const int*)opt_length)[1] == 0);

    long long cs = 0;
    for (int i = 0; i <= o; i++) cs += opt_at(opt_length, is64, i);
    int ohead = PLEN + QLEN + (int)cs;
    int otail = ohead + (int)opt_at(opt_length, is64, o + 1) - 1;

    int pos[6] = {0, PLEN - 1, PLEN, PLEN + QLEN - 1, ohead, otail};

    int h4 = threadIdx.x * 4;        // 256 threads * float4 = 1024
    float4 acc = make_float4(0.f, 0.f, 0.f, 0.f);
    #pragma unroll
    for (int t = 0; t < TRUN; t++) {
        const float* base = emb + (size_t)(t * BSZ + b) * SEQ * HID;
        #pragma unroll
        for (int p = 0; p < 6; p++) {
            float4 v = *(const float4*)(base + (size_t)pos[p] * HID + h4);
            acc.x += v.x; acc.y += v.y; acc.z += v.z; acc.w += v.w;
        }
    }
    const float s = 0.25f;
    *(float4*)(g_feats + (size_t)row * HID + h4) =
        make_float4(acc.x * s, acc.y * s, acc.z * s, acc.w * s);
}

// ---------------------------------------------------------------------------
// 2) Split-K GEMM: out += A(64xK) @ W(KxN). 64x64 tile, K-chunk 32.
//    Grid (16 n-tiles, 32 k-splits) = 512 CTAs, 256 threads, 4x4 micro.
//    As stored transposed [k][row] so both operands read via LDS.128.
//    Epilogue: red.global.add.v4.f32 (vector reduction, no return).
// ---------------------------------------------------------------------------
template <int LAYER>
__global__ void __launch_bounds__(256, 6)
gemm_kernel(const float* __restrict__ W) {
    __shared__ float As[KCHUNK][68];   // [k][row], pitch 68 (16B-aligned, odd bank)
    __shared__ float Ws[KCHUNK][64];   // [k][col]

    const float* A  = (LAYER == 0) ? g_feats : g_h1;
    float*      out = (LAYER == 0) ? g_h1    : g_h2;

    const int n0  = blockIdx.x * NTILE;
    const int k0  = blockIdx.y * KCHUNK;
    const int tid = threadIdx.x;

    // Load A tile 64 rows x 32 k, float4 over k, store transposed.
    {
        int kk4 = (tid & 7) * 4;      // 0..28
        int r   = tid >> 3;           // 0..31
        #pragma unroll
        for (int rr = 0; rr < 2; rr++) {
            int row = r + rr * 32;
            float4 v = *(const float4*)(A + (size_t)row * HID + k0 + kk4);
            if (LAYER == 1) {
                v.x = fmaxf(v.x, 0.f); v.y = fmaxf(v.y, 0.f);
                v.z = fmaxf(v.z, 0.f); v.w = fmaxf(v.w, 0.f);
            }
            As[kk4 + 0][row] = v.x;
            As[kk4 + 1][row] = v.y;
            As[kk4 + 2][row] = v.z;
            As[kk4 + 3][row] = v.w;
        }
    }
    // Load W tile 32 k x 64 n, float4 over n.
    {
        int c4 = (tid & 15) * 4;      // 0..60
        int kk = tid >> 4;            // 0..15
        #pragma unroll
        for (int i = 0; i < 2; i++) {
            int k = kk + i * 16;
            *(float4*)&Ws[k][c4] =
                *(const float4*)(W + (size_t)(k0 + k) * HID + n0 + c4);
        }
    }
    __syncthreads();

    const int c0 = (tid & 15) * 4;
    const int r0 = (tid >> 4) * 4;

    float acc[4][4] = {};
    #pragma unroll
    for (int kk = 0; kk < KCHUNK; kk++) {
        float4 a = *(const float4*)&As[kk][r0];
        float4 w = *(const float4*)&Ws[kk][c0];
        acc[0][0] += a.x * w.x; acc[0][1] += a.x * w.y; acc[0][2] += a.x * w.z; acc[0][3] += a.x * w.w;
        acc[1][0] += a.y * w.x; acc[1][1] += a.y * w.y; acc[1][2] += a.y * w.z; acc[1][3] += a.y * w.w;
        acc[2][0] += a.z * w.x; acc[2][1] += a.z * w.y; acc[2][2] += a.z * w.z; acc[2][3] += a.z * w.w;
        acc[3][0] += a.w * w.x; acc[3][1] += a.w * w.y; acc[3][2] += a.w * w.z; acc[3][3] += a.w * w.w;
    }

    #pragma unroll
    for (int i = 0; i < 4; i++) {
        float* p = out + (size_t)(r0 + i) * HID + n0 + c0;
        asm volatile("red.global.add.v4.f32 [%0], {%1, %2, %3, %4};"
                     :: "l"(p), "f"(acc[i][0]), "f"(acc[i][1]),
                        "f"(acc[i][2]), "f"(acc[i][3]) : "memory");
    }
}

// ---------------------------------------------------------------------------
// 3) fused gemv + log_softmax loss. Single block, 512 threads.
//    logits[row] = relu(g_h2[row]) . W3  (8 threads per row, float4)
// ---------------------------------------------------------------------------
__global__ void gemv_loss_kernel(const float* __restrict__ W3,
                                 const int* __restrict__ y,
                                 float* __restrict__ out, int out_size) {
    __shared__ float logits[ROWS];

    int tid  = threadIdx.x;
    int row  = tid >> 3;             // 0..63
    int lane = tid & 7;              // 0..7

    const float* h = g_h2 + (size_t)row * HID;
    float s = 0.f;
    #pragma unroll
    for (int i = 0; i < 32; i++) {   // 8 lanes * 32 iters * 4 = 1024
        int k = (lane + i * 8) * 4;
        float4 hv = *(const float4*)(h + k);
        float4 wv = *(const float4*)(W3 + k);
        s += fmaxf(hv.x, 0.f) * wv.x + fmaxf(hv.y, 0.f) * wv.y
           + fmaxf(hv.z, 0.f) * wv.z + fmaxf(hv.w, 0.f) * wv.w;
    }
    s += __shfl_down_sync(0xFFFFFFFFu, s, 4);
    s += __shfl_down_sync(0xFFFFFFFFu, s, 2);
    s += __shfl_down_sync(0xFFFFFFFFu, s, 1);
    if (lane == 0) logits[row] = s;
    __syncthreads();

    if (tid < 32) {
        float l[NOPT];
        float loss_part = 0.f;
        if (tid < BSZ) {
            float m = -1e30f;
            #pragma unroll
            for (int o = 0; o < NOPT; o++) {
                l[o] = logits[tid * NOPT + o];
                m = fmaxf(m, l[o]);
            }
            float se = 0.f;
            #pragma unroll
            for (int o = 0; o < NOPT; o++) se += expf(l[o] - m);
            float lse = m + logf(se);
            loss_part = -(l[y[tid]] - lse);

            if (out_size >= ROWS) {
                #pragma unroll
                for (int o = 0; o < NOPT; o++) out[tid * NOPT + o] = l[o];
            }
        }
        #pragma unroll
        for (int off = 16; off; off >>= 1)
            loss_part += __shfl_down_sync(0xFFFFFFFFu, loss_part, off);

        if (tid == 0) {
            float loss = loss_part / (float)BSZ;
            if (out_size == 1)             out[0] = loss;
            else if (out_size >= ROWS + 1) out[ROWS] = loss;
        }
    }
}

// ---------------------------------------------------------------------------
// Launch — 4 kernels total
// inputs: 0=embeddings 1=W1 2=b1 3=W2 4=b2 5=W3 6=y 7=opt_length
// ---------------------------------------------------------------------------
extern "C" void kernel_launch(void* const* d_in, const int* in_sizes, int n_in,
                              void* d_out, int out_size) {
    const float* emb = (const float*)d_in[0];
    const float* W1  = (const float*)d_in[1];
    const float* b1  = (const float*)d_in[2];
    const float* W2  = (const float*)d_in[3];
    const float* b2  = (const float*)d_in[4];
    const float* W3  = (const float*)d_in[5];
    const int*   y   = (const int*)d_in[6];
    const void*  opt = (const void*)d_in[7];
    float* out = (float*)d_out;

    prep_kernel<<<320, 256>>>(emb, opt, b1, b2);
    gemm_kernel<0><<<dim3(16, KSPLIT), 256>>>(W1);
    gemm_kernel<1><<<dim3(16, KSPLIT), 256>>>(W2);
    gemv_loss_kernel<<<1, 512>>>(W3, y, out, out_size);
}

// round 4
// speedup vs baseline: 1.3338x; 1.3338x over previous
#include <cuda_runtime.h>
#include <math.h>

#define HID   1024
#define BSZ   16
#define NOPT  4
#define ROWS  (BSZ*NOPT)    // 64
#define TRUN  2
#define SEQ   1536
#define PLEN  512
#define QLEN  128

#define KSPLIT 32
#define KCHUNK (HID/KSPLIT)   // 32
#define NTILE  64

// Scratch (device globals — no allocation allowed)
__device__ float g_feats[ROWS*HID];
__device__ float g_h1[ROWS*HID];
__device__ float g_h2[ROWS*HID];
__device__ float g_logits[ROWS];

// ---------------------------------------------------------------------------
// opt_length dtype-robust read (harness may store int32 or int64)
// ---------------------------------------------------------------------------
__device__ __forceinline__ long long opt_at(const void* p, bool is64, int i) {
    if (is64) return ((const long long*)p)[i];
    return (long long)((const int*)p)[i];
}

// ---------------------------------------------------------------------------
// 1) prep: blocks [0,256): init g_h1/g_h2 with biases; blocks [256,320): feats
// ---------------------------------------------------------------------------
__global__ void prep_kernel(const float* __restrict__ emb,
                            const void* __restrict__ opt_length,
                            const float* __restrict__ b1,
                            const float* __restrict__ b2) {
    if (blockIdx.x < 256) {
        int i = blockIdx.x * 256 + threadIdx.x;     // 0..65535
        int j = i & (HID - 1);
        g_h1[i] = b1[j];
        g_h2[i] = b2[j];
        return;
    }
    int row = blockIdx.x - 256;      // b*NOPT + o
    int b = row >> 2, o = row & 3;

    bool is64 = (((const int*)opt_length)[1] == 0);

    long long cs = 0;
    for (int i = 0; i <= o; i++) cs += opt_at(opt_length, is64, i);
    int ohead = PLEN + QLEN + (int)cs;
    int otail = ohead + (int)opt_at(opt_length, is64, o + 1) - 1;

    int pos[6] = {0, PLEN - 1, PLEN, PLEN + QLEN - 1, ohead, otail};

    int h4 = threadIdx.x * 4;        // 256 threads * float4 = 1024
    float4 acc = make_float4(0.f, 0.f, 0.f, 0.f);
    #pragma unroll
    for (int t = 0; t < TRUN; t++) {
        const float* base = emb + (size_t)(t * BSZ + b) * SEQ * HID;
        #pragma unroll
        for (int p = 0; p < 6; p++) {
            float4 v = *(const float4*)(base + (size_t)pos[p] * HID + h4);
            acc.x += v.x; acc.y += v.y; acc.z += v.z; acc.w += v.w;
        }
    }
    const float s = 0.25f;
    *(float4*)(g_feats + (size_t)row * HID + h4) =
        make_float4(acc.x * s, acc.y * s, acc.z * s, acc.w * s);
}

// ---------------------------------------------------------------------------
// f32x2 helpers (Blackwell packed fp32 pipe; PTX-only)
// ---------------------------------------------------------------------------
__device__ __forceinline__ unsigned long long bcast_f32x2(float v) {
    unsigned long long r;
    asm("mov.b64 %0, {%1, %1};" : "=l"(r) : "r"(__float_as_uint(v)));
    return r;
}
__device__ __forceinline__ void fma_f32x2(unsigned long long& acc,
                                          unsigned long long a,
                                          unsigned long long b) {
    asm("fma.rn.f32x2 %0, %1, %2, %0;" : "+l"(acc) : "l"(a), "l"(b));
}
__device__ __forceinline__ float lo_f(unsigned long long v) {
    return __uint_as_float((unsigned)(v & 0xFFFFFFFFull));
}
__device__ __forceinline__ float hi_f(unsigned long long v) {
    return __uint_as_float((unsigned)(v >> 32));
}

// ---------------------------------------------------------------------------
// 2) Split-K GEMM: out += A(64xK) @ W(KxN). 64x64 tile, K-chunk 32.
//    Grid (16 n-tiles, 32 k-splits) = 512 CTAs, 256 threads, 4x4 micro.
//    As stored transposed [k][row]; row-pairs come packed for free from a
//    16B LDS, so the inner loop is 2x LDS.128 + 4 mov.b64 + 8 FFMA2.
//    Epilogue: red.global.add.v4.f32 onto bias-initialized out buffer.
// ---------------------------------------------------------------------------
template <int LAYER>
__global__ void __launch_bounds__(256, 6)
gemm_kernel(const float* __restrict__ W) {
    __shared__ float As[KCHUNK][68];   // [k][row], pitch 68 (16B-aligned, odd bank)
    __shared__ float Ws[KCHUNK][64];   // [k][col]

    const float* A  = (LAYER == 0) ? g_feats : g_h1;
    float*      out = (LAYER == 0) ? g_h1    : g_h2;

    const int n0  = blockIdx.x * NTILE;
    const int k0  = blockIdx.y * KCHUNK;
    const int tid = threadIdx.x;

    // Load A tile 64 rows x 32 k, float4 over k, store transposed.
    {
        int kk4 = (tid & 7) * 4;      // 0..28
        int r   = tid >> 3;           // 0..31
        #pragma unroll
        for (int rr = 0; rr < 2; rr++) {
            int row = r + rr * 32;
            float4 v = *(const float4*)(A + (size_t)row * HID + k0 + kk4);
            if (LAYER == 1) {
                v.x = fmaxf(v.x, 0.f); v.y = fmaxf(v.y, 0.f);
                v.z = fmaxf(v.z, 0.f); v.w = fmaxf(v.w, 0.f);
            }
            As[kk4 + 0][row] = v.x;
            As[kk4 + 1][row] = v.y;
            As[kk4 + 2][row] = v.z;
            As[kk4 + 3][row] = v.w;
        }
    }
    // Load W tile 32 k x 64 n, float4 over n.
    {
        int c4 = (tid & 15) * 4;      // 0..60
        int kk = tid >> 4;            // 0..15
        #pragma unroll
        for (int i = 0; i < 2; i++) {
            int k = kk + i * 16;
            *(float4*)&Ws[k][c4] =
                *(const float4*)(W + (size_t)(k0 + k) * HID + n0 + c4);
        }
    }
    __syncthreads();

    const int c0 = (tid & 15) * 4;
    const int r0 = (tid >> 4) * 4;

    // accP[j][h]: col c0+j, h=0 -> rows (r0,r0+1) packed, h=1 -> rows (r0+2,r0+3)
    unsigned long long accP[4][2] = {};
    #pragma unroll
    for (int kk = 0; kk < KCHUNK; kk++) {
        ulonglong2 ap = *(const ulonglong2*)&As[kk][r0];   // packed row pairs (free)
        float4 w = *(const float4*)&Ws[kk][c0];
        unsigned long long w0 = bcast_f32x2(w.x);
        unsigned long long w1 = bcast_f32x2(w.y);
        unsigned long long w2 = bcast_f32x2(w.z);
        unsigned long long w3 = bcast_f32x2(w.w);
        fma_f32x2(accP[0][0], ap.x, w0); fma_f32x2(accP[0][1], ap.y, w0);
        fma_f32x2(accP[1][0], ap.x, w1); fma_f32x2(accP[1][1], ap.y, w1);
        fma_f32x2(accP[2][0], ap.x, w2); fma_f32x2(accP[2][1], ap.y, w2);
        fma_f32x2(accP[3][0], ap.x, w3); fma_f32x2(accP[3][1], ap.y, w3);
    }

    // Unpack to 4 rows x 4 cols and reduce into global.
    #pragma unroll
    for (int i = 0; i < 4; i++) {
        int h = i >> 1;
        float v0 = (i & 1) ? hi_f(accP[0][h]) : lo_f(accP[0][h]);
        float v1 = (i & 1) ? hi_f(accP[1][h]) : lo_f(accP[1][h]);
        float v2 = (i & 1) ? hi_f(accP[2][h]) : lo_f(accP[2][h]);
        float v3 = (i & 1) ? hi_f(accP[3][h]) : lo_f(accP[3][h]);
        float* p = out + (size_t)(r0 + i) * HID + n0 + c0;
        asm volatile("red.global.add.v4.f32 [%0], {%1, %2, %3, %4};"
                     :: "l"(p), "f"(v0), "f"(v1), "f"(v2), "f"(v3) : "memory");
    }
}

// ---------------------------------------------------------------------------
// 3) gemv: 64 blocks, one row each. 256 threads x 1 float4 = 1024 elems.
// ---------------------------------------------------------------------------
__global__ void gemv_kernel(const float* __restrict__ W3) {
    int row = blockIdx.x;
    int tid = threadIdx.x;
    const float* h = g_h2 + (size_t)row * HID;

    float4 hv = *(const float4*)(h + tid * 4);
    float4 wv = *(const float4*)(W3 + tid * 4);
    float s = fmaxf(hv.x, 0.f) * wv.x + fmaxf(hv.y, 0.f) * wv.y
            + fmaxf(hv.z, 0.f) * wv.z + fmaxf(hv.w, 0.f) * wv.w;

    #pragma unroll
    for (int off = 16; off; off >>= 1)
        s += __shfl_down_sync(0xFFFFFFFFu, s, off);

    __shared__ float red[8];
    if ((tid & 31) == 0) red[tid >> 5] = s;
    __syncthreads();
    if (tid == 0) {
        float t = 0.f;
        #pragma unroll
        for (int i = 0; i < 8; i++) t += red[i];
        g_logits[row] = t;
    }
}

// ---------------------------------------------------------------------------
// 4) result + log_softmax loss (tiny)
// ---------------------------------------------------------------------------
__global__ void loss_kernel(const int* __restrict__ y, float* __restrict__ out,
                            int out_size) {
    int tid = threadIdx.x;   // 32 threads
    float l[NOPT];
    float loss_part = 0.f;
    if (tid < BSZ) {
        float m = -1e30f;
        #pragma unroll
        for (int o = 0; o < NOPT; o++) {
            l[o] = g_logits[tid * NOPT + o];
            m = fmaxf(m, l[o]);
        }
        float se = 0.f;
        #pragma unroll
        for (int o = 0; o < NOPT; o++) se += expf(l[o] - m);
        float lse = m + logf(se);
        loss_part = -(l[y[tid]] - lse);

        if (out_size >= ROWS) {
            #pragma unroll
            for (int o = 0; o < NOPT; o++) out[tid * NOPT + o] = l[o];
        }
    }
    #pragma unroll
    for (int off = 16; off; off >>= 1)
        loss_part += __shfl_down_sync(0xFFFFFFFFu, loss_part, off);

    if (tid == 0) {
        float loss = loss_part / (float)BSZ;
        if (out_size == 1)             out[0] = loss;
        else if (out_size >= ROWS + 1) out[ROWS] = loss;
    }
}

// ---------------------------------------------------------------------------
// Launch — 5 kernels
// inputs: 0=embeddings 1=W1 2=b1 3=W2 4=b2 5=W3 6=y 7=opt_length
// ---------------------------------------------------------------------------
extern "C" void kernel_launch(void* const* d_in, const int* in_sizes, int n_in,
                              void* d_out, int out_size) {
    const float* emb = (const float*)d_in[0];
    const float* W1  = (const float*)d_in[1];
    const float* b1  = (const float*)d_in[2];
    const float* W2  = (const float*)d_in[3];
    const float* b2  = (const float*)d_in[4];
    const float* W3  = (const float*)d_in[5];
    const int*   y   = (const int*)d_in[6];
    const void*  opt = (const void*)d_in[7];
    float* out = (float*)d_out;

    prep_kernel<<<320, 256>>>(emb, opt, b1, b2);
    gemm_kernel<0><<<dim3(16, KSPLIT), 256>>>(W1);
    gemm_kernel<1><<<dim3(16, KSPLIT), 256>>>(W2);
    gemv_kernel<<<ROWS, 256>>>(W3);
    loss_kernel<<<1, 32>>>(y, out, out_size);
}